// round 3
// baseline (speedup 1.0000x reference)
#include <cuda_runtime.h>
#include <cuda_bf16.h>
#include <cstdint>

#define VOCAB 50000
#define DMODEL 256
#define NCELLS (4 * 64 * 64)   // 16384
#define NTOK 32

__device__ float g_proj[VOCAB];

// ---------------------------------------------------------------------------
// Kernel 1: p[v] = dot(E[v,:], W). One warp handles FOUR vocab rows
// -> 8 outstanding LDG.128 per thread, streaming E once (L2/HBM-bound).
// ---------------------------------------------------------------------------
__global__ void __launch_bounds__(256) proj_kernel(
    const float* __restrict__ E,
    const float* __restrict__ W)
{
    int gwarp = (blockIdx.x * blockDim.x + threadIdx.x) >> 5;
    int lane  = threadIdx.x & 31;
    int row0  = gwarp * 4;
    if (row0 >= VOCAB) return;

    const float4* __restrict__ e4 = reinterpret_cast<const float4*>(E);
    const float4* __restrict__ w4 = reinterpret_cast<const float4*>(W);

    float4 wa = w4[lane];
    float4 wb = w4[lane + 32];

    // Front-batch 8 independent LDG.128 (2 per row x 4 rows)
    float4 r0a = e4[(size_t)(row0 + 0) * 64 + lane];
    float4 r0b = e4[(size_t)(row0 + 0) * 64 + lane + 32];
    float4 r1a = e4[(size_t)(row0 + 1) * 64 + lane];
    float4 r1b = e4[(size_t)(row0 + 1) * 64 + lane + 32];
    float4 r2a = e4[(size_t)(row0 + 2) * 64 + lane];
    float4 r2b = e4[(size_t)(row0 + 2) * 64 + lane + 32];
    float4 r3a = e4[(size_t)(row0 + 3) * 64 + lane];
    float4 r3b = e4[(size_t)(row0 + 3) * 64 + lane + 32];

    float s0 = 0.f, s1 = 0.f, s2 = 0.f, s3 = 0.f;
    s0 = fmaf(r0a.x, wa.x, s0); s0 = fmaf(r0a.y, wa.y, s0);
    s0 = fmaf(r0a.z, wa.z, s0); s0 = fmaf(r0a.w, wa.w, s0);
    s0 = fmaf(r0b.x, wb.x, s0); s0 = fmaf(r0b.y, wb.y, s0);
    s0 = fmaf(r0b.z, wb.z, s0); s0 = fmaf(r0b.w, wb.w, s0);

    s1 = fmaf(r1a.x, wa.x, s1); s1 = fmaf(r1a.y, wa.y, s1);
    s1 = fmaf(r1a.z, wa.z, s1); s1 = fmaf(r1a.w, wa.w, s1);
    s1 = fmaf(r1b.x, wb.x, s1); s1 = fmaf(r1b.y, wb.y, s1);
    s1 = fmaf(r1b.z, wb.z, s1); s1 = fmaf(r1b.w, wb.w, s1);

    s2 = fmaf(r2a.x, wa.x, s2); s2 = fmaf(r2a.y, wa.y, s2);
    s2 = fmaf(r2a.z, wa.z, s2); s2 = fmaf(r2a.w, wa.w, s2);
    s2 = fmaf(r2b.x, wb.x, s2); s2 = fmaf(r2b.y, wb.y, s2);
    s2 = fmaf(r2b.z, wb.z, s2); s2 = fmaf(r2b.w, wb.w, s2);

    s3 = fmaf(r3a.x, wa.x, s3); s3 = fmaf(r3a.y, wa.y, s3);
    s3 = fmaf(r3a.z, wa.z, s3); s3 = fmaf(r3a.w, wa.w, s3);
    s3 = fmaf(r3b.x, wb.x, s3); s3 = fmaf(r3b.y, wb.y, s3);
    s3 = fmaf(r3b.z, wb.z, s3); s3 = fmaf(r3b.w, wb.w, s3);

    #pragma unroll
    for (int o = 16; o > 0; o >>= 1) {
        s0 += __shfl_xor_sync(0xFFFFFFFFu, s0, o);
        s1 += __shfl_xor_sync(0xFFFFFFFFu, s1, o);
        s2 += __shfl_xor_sync(0xFFFFFFFFu, s2, o);
        s3 += __shfl_xor_sync(0xFFFFFFFFu, s3, o);
    }
    if (lane == 0) {
        g_proj[row0 + 0] = s0;
        g_proj[row0 + 1] = s1;
        g_proj[row0 + 2] = s2;
        g_proj[row0 + 3] = s3;
    }
}

// ---------------------------------------------------------------------------
// Kernel 2: out[cell] = sum_t p[x[cell,t]] + bias.
// The 195.3 KB proj table is staged into dynamic SMEM per block; gathers
// become LDS (bank-conflict cost ~3 cyc/32 scalars) instead of L1tex
// wavefront-serialized LDG. 64 blocks x 512 threads, grid-stride over cells.
// Layout per warp-iteration: 4 cells, 8 lanes/cell, each lane int4 (4 tokens).
// ---------------------------------------------------------------------------
__global__ void __launch_bounds__(512) gather_kernel(
    const int* __restrict__ x,
    const float* __restrict__ bias,
    float* __restrict__ out)
{
    extern __shared__ float s_proj[];   // VOCAB floats = 200000 B

    // Fill: 12500 float4 from the (L2-resident) global table
    const float4* __restrict__ g4 = reinterpret_cast<const float4*>(g_proj);
    float4* s4 = reinterpret_cast<float4*>(s_proj);
    for (int i = threadIdx.x; i < VOCAB / 4; i += blockDim.x)
        s4[i] = g4[i];
    __syncthreads();

    float bv = bias[0];

    int lane   = threadIdx.x & 31;
    int warp   = (blockIdx.x * blockDim.x + threadIdx.x) >> 5;
    int nwarps = (gridDim.x * blockDim.x) >> 5;
    int sub    = lane & 7;

    const int4* __restrict__ x4 = reinterpret_cast<const int4*>(x);

    // cell-quads: 4 cells per warp-iteration (warp reads 32 consecutive int4)
    for (int q = warp; q < NCELLS / 4; q += nwarps) {
        int4 t = x4[q * 32 + lane];

        float s = s_proj[t.x] + s_proj[t.y] + s_proj[t.z] + s_proj[t.w];

        s += __shfl_xor_sync(0xFFFFFFFFu, s, 4);
        s += __shfl_xor_sync(0xFFFFFFFFu, s, 2);
        s += __shfl_xor_sync(0xFFFFFFFFu, s, 1);

        if (sub == 0) out[q * 4 + (lane >> 3)] = s + bv;
    }
}

extern "C" void kernel_launch(void* const* d_in, const int* in_sizes, int n_in,
                              void* d_out, int out_size)
{
    const int*   x = (const int*)  d_in[0];
    const float* E = (const float*)d_in[1];
    const float* W = (const float*)d_in[2];
    const float* b = (const float*)d_in[3];
    float* out = (float*)d_out;

    static bool attr_done = false;
    if (!attr_done) {
        cudaFuncSetAttribute(gather_kernel,
                             cudaFuncAttributeMaxDynamicSharedMemorySize,
                             VOCAB * (int)sizeof(float));
        attr_done = true;
    }

    // proj: 12500 warps (4 rows each) -> 1563 blocks of 256
    proj_kernel<<<(VOCAB / 4 + 7) / 8, 256>>>(E, W);
    // gather: 64 blocks x 512 threads, 195.3 KB dynamic smem each
    gather_kernel<<<64, 512, VOCAB * sizeof(float)>>>(x, b, out);
}

// round 4
// speedup vs baseline: 1.2046x; 1.2046x over previous
#include <cuda_runtime.h>
#include <cuda_bf16.h>
#include <cstdint>

#define VOCAB 50000
#define DMODEL 256
#define NCELLS (4 * 64 * 64)   // 16384
#define NTOK 32

__device__ float g_proj[VOCAB];

// ---------------------------------------------------------------------------
// Kernel 1: p[v] = dot(E[v,:], W). One warp per FOUR vocab rows
// (8 outstanding LDG.128/thread). L2-bandwidth bound (E L2-resident).
// ---------------------------------------------------------------------------
__global__ void __launch_bounds__(256) proj_kernel(
    const float* __restrict__ E,
    const float* __restrict__ W)
{
    int gwarp = (blockIdx.x * blockDim.x + threadIdx.x) >> 5;
    int lane  = threadIdx.x & 31;
    int row0  = gwarp * 4;
    if (row0 >= VOCAB) return;

    const float4* __restrict__ e4 = reinterpret_cast<const float4*>(E);
    const float4* __restrict__ w4 = reinterpret_cast<const float4*>(W);

    float4 wa = w4[lane];
    float4 wb = w4[lane + 32];

    float4 r0a = e4[(size_t)(row0 + 0) * 64 + lane];
    float4 r0b = e4[(size_t)(row0 + 0) * 64 + lane + 32];
    float4 r1a = e4[(size_t)(row0 + 1) * 64 + lane];
    float4 r1b = e4[(size_t)(row0 + 1) * 64 + lane + 32];
    float4 r2a = e4[(size_t)(row0 + 2) * 64 + lane];
    float4 r2b = e4[(size_t)(row0 + 2) * 64 + lane + 32];
    float4 r3a = e4[(size_t)(row0 + 3) * 64 + lane];
    float4 r3b = e4[(size_t)(row0 + 3) * 64 + lane + 32];

    float s0 = 0.f, s1 = 0.f, s2 = 0.f, s3 = 0.f;
    s0 = fmaf(r0a.x, wa.x, s0); s0 = fmaf(r0a.y, wa.y, s0);
    s0 = fmaf(r0a.z, wa.z, s0); s0 = fmaf(r0a.w, wa.w, s0);
    s0 = fmaf(r0b.x, wb.x, s0); s0 = fmaf(r0b.y, wb.y, s0);
    s0 = fmaf(r0b.z, wb.z, s0); s0 = fmaf(r0b.w, wb.w, s0);

    s1 = fmaf(r1a.x, wa.x, s1); s1 = fmaf(r1a.y, wa.y, s1);
    s1 = fmaf(r1a.z, wa.z, s1); s1 = fmaf(r1a.w, wa.w, s1);
    s1 = fmaf(r1b.x, wb.x, s1); s1 = fmaf(r1b.y, wb.y, s1);
    s1 = fmaf(r1b.z, wb.z, s1); s1 = fmaf(r1b.w, wb.w, s1);

    s2 = fmaf(r2a.x, wa.x, s2); s2 = fmaf(r2a.y, wa.y, s2);
    s2 = fmaf(r2a.z, wa.z, s2); s2 = fmaf(r2a.w, wa.w, s2);
    s2 = fmaf(r2b.x, wb.x, s2); s2 = fmaf(r2b.y, wb.y, s2);
    s2 = fmaf(r2b.z, wb.z, s2); s2 = fmaf(r2b.w, wb.w, s2);

    s3 = fmaf(r3a.x, wa.x, s3); s3 = fmaf(r3a.y, wa.y, s3);
    s3 = fmaf(r3a.z, wa.z, s3); s3 = fmaf(r3a.w, wa.w, s3);
    s3 = fmaf(r3b.x, wb.x, s3); s3 = fmaf(r3b.y, wb.y, s3);
    s3 = fmaf(r3b.z, wb.z, s3); s3 = fmaf(r3b.w, wb.w, s3);

    #pragma unroll
    for (int o = 16; o > 0; o >>= 1) {
        s0 += __shfl_xor_sync(0xFFFFFFFFu, s0, o);
        s1 += __shfl_xor_sync(0xFFFFFFFFu, s1, o);
        s2 += __shfl_xor_sync(0xFFFFFFFFu, s2, o);
        s3 += __shfl_xor_sync(0xFFFFFFFFu, s3, o);
    }
    if (lane == 0) {
        g_proj[row0 + 0] = s0;
        g_proj[row0 + 1] = s1;
        g_proj[row0 + 2] = s2;
        g_proj[row0 + 3] = s3;
    }
}

// ---------------------------------------------------------------------------
// Kernel 2: out[cell] = sum_t p[x[cell,t]] + bias.
// 128 blocks x 1024 threads (1 block/SM, 32 warps). Each block stages the
// 195.3 KB table into dynamic smem via cp.async (fire-and-forget), loads its
// x int4 quad UNDER the fill, then does LDS gathers (conflict-degree cost
// only) + 3-step 8-lane reduction. Exactly 1 cell-quad per warp.
// ---------------------------------------------------------------------------
__global__ void __launch_bounds__(1024) gather_kernel(
    const int* __restrict__ x,
    const float* __restrict__ bias,
    float* __restrict__ out)
{
    extern __shared__ float s_proj[];   // VOCAB floats = 200000 B

    // Async fill: 12500 x 16B cp.async per block (~13 per thread)
    uint32_t sbase;
    {
        uint64_t tmp = __cvta_generic_to_shared(s_proj);
        sbase = (uint32_t)tmp;
    }
    const float4* __restrict__ g4 = reinterpret_cast<const float4*>(g_proj);
    for (int i = threadIdx.x; i < VOCAB / 4; i += 1024) {
        asm volatile("cp.async.cg.shared.global [%0], [%1], 16;\n"
                     :: "r"(sbase + i * 16), "l"(g4 + i));
    }
    asm volatile("cp.async.commit_group;\n");

    // Load x and bias while the fill is in flight (independent of smem)
    int wid  = threadIdx.x >> 5;
    int lane = threadIdx.x & 31;
    int gw   = blockIdx.x * 32 + wid;           // 0..4095 == NCELLS/4-1
    int4 t   = reinterpret_cast<const int4*>(x)[gw * 32 + lane];
    float bv = bias[0];

    asm volatile("cp.async.wait_group 0;\n" ::: "memory");
    __syncthreads();

    float s = s_proj[t.x] + s_proj[t.y] + s_proj[t.z] + s_proj[t.w];

    s += __shfl_xor_sync(0xFFFFFFFFu, s, 4);
    s += __shfl_xor_sync(0xFFFFFFFFu, s, 2);
    s += __shfl_xor_sync(0xFFFFFFFFu, s, 1);

    if ((lane & 7) == 0) out[gw * 4 + (lane >> 3)] = s + bv;
}

extern "C" void kernel_launch(void* const* d_in, const int* in_sizes, int n_in,
                              void* d_out, int out_size)
{
    const int*   x = (const int*)  d_in[0];
    const float* E = (const float*)d_in[1];
    const float* W = (const float*)d_in[2];
    const float* b = (const float*)d_in[3];
    float* out = (float*)d_out;

    static bool attr_done = false;
    if (!attr_done) {
        cudaFuncSetAttribute(gather_kernel,
                             cudaFuncAttributeMaxDynamicSharedMemorySize,
                             VOCAB * (int)sizeof(float));
        attr_done = true;
    }

    // proj: 12500 warps (4 rows each) -> 1563 blocks of 256
    proj_kernel<<<(VOCAB / 4 + 7) / 8, 256>>>(E, W);
    // gather: 128 blocks x 1024 threads, exactly one cell-quad per warp
    gather_kernel<<<128, 1024, VOCAB * sizeof(float)>>>(x, b, out);
}